// round 12
// baseline (speedup 1.0000x reference)
#include <cuda_runtime.h>
#include <stdint.h>

#define N_WORDS    8
#define HASH_BITS  11
#define HASH_SIZE  (1 << HASH_BITS)    // 2048 slots
#define HASH_MASK  (HASH_SIZE - 1)
#define THREADS    704                 // 22 warps; 143 blocks covers 100k rows
#define MAX_BLOCKS 148

__device__ __forceinline__ uint32_t slot_of(uint32_t w0) {
    return (w0 * 0x9E3779B1u) >> (32 - HASH_BITS);
}

template <bool VEC>
__device__ __forceinline__ uint2 load_w01(const int* __restrict__ p) {
    if (VEC) { int2 v = __ldg(reinterpret_cast<const int2*>(p)); return make_uint2((uint32_t)v.x, (uint32_t)v.y); }
    return make_uint2((uint32_t)__ldg(p), (uint32_t)__ldg(p + 1));
}

template <bool VEC>
__device__ __forceinline__ void load_full(const int* __restrict__ p, uint32_t k[N_WORDS]) {
    if (VEC) {
        int4 a = __ldg(reinterpret_cast<const int4*>(p));
        int4 b = __ldg(reinterpret_cast<const int4*>(p) + 1);
        k[0]=(uint32_t)a.x; k[1]=(uint32_t)a.y; k[2]=(uint32_t)a.z; k[3]=(uint32_t)a.w;
        k[4]=(uint32_t)b.x; k[5]=(uint32_t)b.y; k[6]=(uint32_t)b.z; k[7]=(uint32_t)b.w;
    } else {
        #pragma unroll
        for (int j = 0; j < N_WORDS; ++j) k[j] = (uint32_t)__ldg(p + j);
    }
}

template <bool VEC>
__global__ __launch_bounds__(THREADS)
void encode_kernel(const int* __restrict__ x,
                   const int* __restrict__ classes,
                   float* __restrict__ out,
                   int n_rows, int n_classes) {
    __shared__ unsigned long long s_fp[HASH_SIZE];   // 16 KB: fingerprint, 0 = empty
    __shared__ uint16_t           s_idx[HASH_SIZE];  //  4 KB: class idx (CAS winner writes)
    __shared__ int                s_dup;

    const int tid = threadIdx.x;

    // 0) Prefetch this thread's query pair at instruction 0: its latency
    //    overlaps the entire init+build+barrier sequence below.
    const int r0 = blockIdx.x * THREADS + tid;
    uint2 wq = make_uint2(0u, 0u);
    if (r0 < n_rows) wq = load_w01<VEC>(x + (size_t)r0 * N_WORDS);

    // 1) Init.
    for (int i = tid; i < HASH_SIZE; i += THREADS) s_fp[i] = 0ull;
    if (tid == 0) s_dup = 0;
    __syncthreads();

    // 2) Build with single 64-bit CAS; duplicate fingerprints are detected
    //    atomically (CAS observes our own fp already present in the chain).
    const int nc_ins = (n_classes < HASH_SIZE - 1) ? n_classes : HASH_SIZE - 1;
    for (int c = tid; c < nc_ins; c += THREADS) {
        uint2 w = load_w01<VEC>(classes + (size_t)c * N_WORDS);
        unsigned long long fp = ((unsigned long long)w.y << 32) | w.x;
        if (fp == 0ull) { s_dup = 1; continue; }     // 2^-64 corner: exact path
        uint32_t h = slot_of(w.x);
        for (int p = 0; p < HASH_SIZE; ++p) {
            unsigned long long old = atomicCAS(&s_fp[h], 0ull, fp);
            if (old == 0ull) { s_idx[h] = (uint16_t)c; break; }  // claimed
            if (old == fp)   { s_dup = 1; break; }               // dup fp -> exact path
            h = (h + 1) & HASH_MASK;
        }
    }
    if (n_classes > nc_ins && tid == 0) s_dup = 1;   // overflow -> exact path
    __syncthreads();   // publishes s_fp, s_idx, s_dup

    const bool dup = (s_dup != 0);
    const int stride = gridDim.x * THREADS;

    // 3) Lookup (x pair already in registers for the first row).
    for (int r = r0; r < n_rows; r += stride) {
        uint2 w = (r == r0) ? wq : load_w01<VEC>(x + (size_t)r * N_WORDS);
        unsigned long long fp = ((unsigned long long)w.y << 32) | w.x;

        int result = -1;
        if (!dup) {
            uint32_t h = slot_of(w.x);
            for (int p = 0; p < HASH_SIZE; ++p) {
                unsigned long long e = s_fp[h];      // LDS.64
                if (e == 0ull) break;                // miss -> exact fallback
                if (e == fp) { result = (int)s_idx[h]; break; }
                h = (h + 1) & HASH_MASK;
            }
        }

        // Exact fallback (dup flag, fp==0 query, miss, or overflow):
        // first ascending full match == argmax semantics; 0 if none.
        if (result < 0) {
            uint32_t k[N_WORDS];
            load_full<VEC>(x + (size_t)r * N_WORDS, k);
            for (int c = 0; c < n_classes; ++c) {
                uint32_t ck[N_WORDS];
                load_full<VEC>(classes + (size_t)c * N_WORDS, ck);
                bool match = true;
                #pragma unroll
                for (int j = 0; j < N_WORDS; ++j) match &= (ck[j] == k[j]);
                if (match) { result = c; break; }
            }
            if (result < 0) result = 0;
        }

        out[r] = (float)result;
    }
}

extern "C" void kernel_launch(void* const* d_in, const int* in_sizes, int n_in,
                              void* d_out, int out_size) {
    // x is the large input (one output per row); classes_table is the small one.
    int xi = 0, ci = 1;
    if (n_in >= 2 && in_sizes[1] > in_sizes[0]) { xi = 1; ci = 0; }

    const int* x       = (const int*)d_in[xi];
    const int* classes = (const int*)d_in[ci];
    float* out         = (float*)d_out;

    int rows_from_x = in_sizes[xi] / N_WORDS;
    int n_rows = (out_size < rows_from_x) ? out_size : rows_from_x;
    int n_classes = in_sizes[ci] / N_WORDS;

    int blocks_needed = (n_rows + THREADS - 1) / THREADS;
    int blocks = (blocks_needed < MAX_BLOCKS) ? blocks_needed : MAX_BLOCKS;
    if (blocks < 1) blocks = 1;

    const bool vec = ((((uintptr_t)x) & 15u) == 0) && ((((uintptr_t)classes) & 15u) == 0);
    if (vec) encode_kernel<true ><<<blocks, THREADS>>>(x, classes, out, n_rows, n_classes);
    else     encode_kernel<false><<<blocks, THREADS>>>(x, classes, out, n_rows, n_classes);
}